// round 7
// baseline (speedup 1.0000x reference)
#include <cuda_runtime.h>
#include <cuda_bf16.h>
#include <cstdint>

// Problem: T=256, B=64, E=512, H=512, HD=256, L=2, K=7
#define NEG_ -10000.0f

// ---------------- device scratch (no cudaMalloc allowed) ----------------
__device__ float g_x [16384*512];   // embedded input (layer0 GEMM A)
__device__ float g_y0[16384*512];   // layer0 hidden output [m][dir*256+hd]
__device__ float g_y1[16384*512];   // layer1 hidden output
__device__ float g_xg[16384*2048];  // input-gate preacts [m][dir*1024 + gate*256 + hd]
__device__ float g_feats[16384*7];
__device__ float g_hstate[2*2*64*256]; // [parity][dir][b][hd]

// smem sizes
#define LSTM_SMEM_BYTES ((128*260 + 2*8*260) * 4)   /* 149760 */
#define VIT_SMEM_BYTES  (256*64*4)                  /* 65536  */

// ============================================================
// 1) Embedding gather: g_x[t*64+b][:] = emb[sent[t*64+b]][:]
// ============================================================
__global__ void __launch_bounds__(256) embed_kernel(const int* __restrict__ sent,
                                                    const float* __restrict__ emb)
{
    int gw   = (blockIdx.x * 256 + threadIdx.x) >> 5;
    int lane = threadIdx.x & 31;
    int nw   = gridDim.x * 8;
    for (int row = gw; row < 16384; row += nw) {
        int tok = sent[row];
        const float4* s = (const float4*)(emb + (size_t)tok * 512);
        float4*       d = (float4*)(g_x + (size_t)row * 512);
        #pragma unroll
        for (int i = 0; i < 4; i++) d[lane + i * 32] = s[lane + i * 32];
    }
}

// ============================================================
// 2) GEMM: g_xg[m][n] = A[m][:] . W[n][:] + b1[n] + b2[n]
//    A = g_x (layer0) or g_y0 (layer1), [16384][512]
//    W = w_ih[l] as [2048][512] row-major
//    128x128 tile, BK=8, 256 threads, 8x8 microtile (split 4+4)
// ============================================================
__global__ void __launch_bounds__(256, 2)
gemm_kernel(const float* __restrict__ W, const float* __restrict__ b1,
            const float* __restrict__ b2, int layer)
{
    const float* A = layer ? g_y0 : g_x;
    __shared__ float As[8][132];
    __shared__ float Bs[8][132];

    int tid  = threadIdx.x;
    int m0   = blockIdx.y * 128;
    int n0   = blockIdx.x * 128;
    int lrow = tid >> 1;            // 0..127
    int kc   = (tid & 1) * 4;       // 0 or 4
    const float* Ap = A + (size_t)(m0 + lrow) * 512 + kc;
    const float* Wp = W + (size_t)(n0 + lrow) * 512 + kc;
    int tr = tid >> 4;              // 0..15
    int tc = tid & 15;              // 0..15

    float acc[8][8];
    #pragma unroll
    for (int i = 0; i < 8; i++)
        #pragma unroll
        for (int j = 0; j < 8; j++) acc[i][j] = 0.f;

    float4 pa = *(const float4*)Ap;
    float4 pb = *(const float4*)Wp;

    for (int kt = 0; kt < 64; kt++) {
        __syncthreads();
        As[kc + 0][lrow] = pa.x; As[kc + 1][lrow] = pa.y;
        As[kc + 2][lrow] = pa.z; As[kc + 3][lrow] = pa.w;
        Bs[kc + 0][lrow] = pb.x; Bs[kc + 1][lrow] = pb.y;
        Bs[kc + 2][lrow] = pb.z; Bs[kc + 3][lrow] = pb.w;
        __syncthreads();
        if (kt < 63) {
            pa = *(const float4*)(Ap + (kt + 1) * 8);
            pb = *(const float4*)(Wp + (kt + 1) * 8);
        }
        #pragma unroll
        for (int kk = 0; kk < 8; kk++) {
            float4 alo = *(const float4*)&As[kk][tr * 4];
            float4 ahi = *(const float4*)&As[kk][64 + tr * 4];
            float4 blo = *(const float4*)&Bs[kk][tc * 4];
            float4 bhi = *(const float4*)&Bs[kk][64 + tc * 4];
            float av[8] = {alo.x, alo.y, alo.z, alo.w, ahi.x, ahi.y, ahi.z, ahi.w};
            float bv[8] = {blo.x, blo.y, blo.z, blo.w, bhi.x, bhi.y, bhi.z, bhi.w};
            #pragma unroll
            for (int i = 0; i < 8; i++)
                #pragma unroll
                for (int j = 0; j < 8; j++) acc[i][j] += av[i] * bv[j];
        }
    }

    #pragma unroll
    for (int i = 0; i < 8; i++) {
        int r = m0 + ((i < 4) ? (tr * 4 + i) : (64 + tr * 4 + i - 4));
        #pragma unroll
        for (int jh = 0; jh < 2; jh++) {
            int cb = n0 + jh * 64 + tc * 4;
            float4 o;
            o.x = acc[i][jh * 4 + 0] + b1[cb + 0] + b2[cb + 0];
            o.y = acc[i][jh * 4 + 1] + b1[cb + 1] + b2[cb + 1];
            o.z = acc[i][jh * 4 + 2] + b1[cb + 2] + b2[cb + 2];
            o.w = acc[i][jh * 4 + 3] + b1[cb + 3] + b2[cb + 3];
            *(float4*)(g_xg + (size_t)r * 2048 + cb) = o;
        }
    }
}

// ============================================================
// 3) LSTM recurrence, one layer (both directions).
//    128 CTAs = 16 clusters of 8. cluster = (dir, batch-chunk of 8).
//    CTA rank r owns hd in [r*32, r*32+32) for all 4 gates.
//    W_hh slice (128 rows x 256) in smem fp32, padded rows (65 float4).
//    h exchanged via gmem (g_hstate) + barrier.cluster each step.
// ============================================================
__device__ __forceinline__ float sigf(float x) { return 1.0f / (1.0f + __expf(-x)); }

__global__ void __cluster_dims__(8, 1, 1) __launch_bounds__(256, 1)
lstm_kernel(const float* __restrict__ w_hh,   // layer base: [2][1024][256]
            const float* __restrict__ h0,     // [4][64][256]
            const float* __restrict__ c0,
            int layer)
{
    extern __shared__ float smem[];
    float* W_s   = smem;                 // 128 rows x 260 floats (padded)
    float* h_loc = smem + 128 * 260;     // [2 parity][8 b][260 floats]
    const int GSTR = 260;

    float* y = layer ? g_y1 : g_y0;

    int bx  = blockIdx.x;
    int cid = bx >> 3;                   // cluster id 0..15
    int r   = bx & 7;                    // rank = hd-chunk
    int dir = cid & 1;
    int bc  = cid >> 1;                  // batch chunk 0..7
    int tid = threadIdx.x;
    int hd  = tid >> 3;                  // 0..31
    int b   = tid & 7;                   // 0..7
    int hd_g = r * 32 + hd;              // 0..255
    int b_g  = bc * 8 + b;               // 0..63

    // load W_hh slice: local row = gate*32 + hd  ->  global row gate*256 + hd_g
    const float* Wd = w_hh + (size_t)dir * 1024 * 256;
    for (int i = tid; i < 128 * 64; i += 256) {
        int row = i >> 6, k4 = i & 63;
        int grow = (row >> 5) * 256 + r * 32 + (row & 31);
        float4 v = *(const float4*)(Wd + (size_t)grow * 256 + k4 * 4);
        *(float4*)(W_s + row * GSTR + k4 * 4) = v;
    }
    // initial h gather from h0 row (2*layer+dir), batches bc*8..bc*8+7
    const float* h0d = h0 + ((size_t)(2 * layer + dir) * 64 + bc * 8) * 256;
    for (int i = tid; i < 512; i += 256) {
        int row = i >> 6, k4 = i & 63;
        float4 v = *(const float4*)(h0d + row * 256 + k4 * 4);
        *(float4*)(h_loc + row * GSTR + k4 * 4) = v;
    }
    float c = c0[((size_t)(2 * layer + dir) * 64 + b_g) * 256 + hd_g];
    __syncthreads();

    const float* w0r = W_s + (hd) * GSTR;
    const float* w1r = W_s + (32 + hd) * GSTR;
    const float* w2r = W_s + (64 + hd) * GSTR;
    const float* w3r = W_s + (96 + hd) * GSTR;

    for (int s = 0; s < 256; s++) {
        int t = dir ? (255 - s) : s;
        int p = s & 1;
        const float* hrow = h_loc + p * 8 * GSTR + b * GSTR;

        // prefetch input-gate preacts
        size_t xb = ((size_t)t * 64 + b_g) * 2048 + (size_t)dir * 1024 + hd_g;
        float xg0 = g_xg[xb];
        float xg1 = g_xg[xb + 256];
        float xg2 = g_xg[xb + 512];
        float xg3 = g_xg[xb + 768];

        float a0 = 0.f, a1 = 0.f, a2 = 0.f, a3 = 0.f;
        #pragma unroll 8
        for (int k4 = 0; k4 < 64; k4++) {
            float4 hv = *(const float4*)(hrow + k4 * 4);
            float4 w0 = *(const float4*)(w0r + k4 * 4);
            float4 w1 = *(const float4*)(w1r + k4 * 4);
            float4 w2 = *(const float4*)(w2r + k4 * 4);
            float4 w3 = *(const float4*)(w3r + k4 * 4);
            a0 += w0.x * hv.x + w0.y * hv.y + w0.z * hv.z + w0.w * hv.w;
            a1 += w1.x * hv.x + w1.y * hv.y + w1.z * hv.z + w1.w * hv.w;
            a2 += w2.x * hv.x + w2.y * hv.y + w2.z * hv.z + w2.w * hv.w;
            a3 += w3.x * hv.x + w3.y * hv.y + w3.z * hv.z + w3.w * hv.w;
        }
        float ig = sigf(a0 + xg0);
        float fg = sigf(a1 + xg1);
        float gg = tanhf(a2 + xg2);
        float og = sigf(a3 + xg3);
        c = fg * c + ig * gg;
        float h = og * tanhf(c);

        // write layer output
        y[((size_t)t * 64 + b_g) * 512 + (size_t)dir * 256 + hd_g] = h;

        // publish h for next step
        int wp = (s + 1) & 1;
        g_hstate[(((size_t)wp * 2 + dir) * 64 + b_g) * 256 + hd_g] = h;
        __threadfence();
        asm volatile("barrier.cluster.arrive.aligned;" ::: "memory");
        asm volatile("barrier.cluster.wait.aligned;"   ::: "memory");

        // gather full h (8 batches x 256) into h_loc[wp]
        const float* src = g_hstate + ((size_t)wp * 2 + dir) * 64 * 256 + (size_t)bc * 8 * 256;
        for (int i = tid; i < 512; i += 256) {
            int row = i >> 6, k4 = i & 63;
            float4 v = __ldcg((const float4*)(src + row * 256 + k4 * 4));
            *(float4*)(h_loc + wp * 8 * GSTR + row * GSTR + k4 * 4) = v;
        }
        __syncthreads();
    }
}

// ============================================================
// 4) hidden2tag: g_feats[m][k] = g_y1[m][:] . w_out[k][:] + b_out[k]
// ============================================================
__global__ void __launch_bounds__(256)
feats_kernel(const float* __restrict__ w_out, const float* __restrict__ b_out)
{
    __shared__ float ws[7 * 512];
    __shared__ float bs[7];
    int tid = threadIdx.x;
    for (int i = tid; i < 3584; i += 256) ws[i] = w_out[i];
    if (tid < 7) bs[tid] = b_out[tid];
    __syncthreads();

    int gw   = (blockIdx.x * 256 + tid) >> 5;
    int lane = tid & 31;
    int nw   = gridDim.x * 8;
    for (int m = gw; m < 16384; m += nw) {
        const float4* y4 = (const float4*)(g_y1 + (size_t)m * 512);
        float acc[7] = {0, 0, 0, 0, 0, 0, 0};
        #pragma unroll
        for (int q = 0; q < 4; q++) {
            int k4 = q * 32 + lane;
            float4 yv = y4[k4];
            #pragma unroll
            for (int tg = 0; tg < 7; tg++) {
                float4 wv = *(const float4*)(ws + tg * 512 + k4 * 4);
                acc[tg] += yv.x * wv.x + yv.y * wv.y + yv.z * wv.z + yv.w * wv.w;
            }
        }
        #pragma unroll
        for (int tg = 0; tg < 7; tg++) {
            #pragma unroll
            for (int off = 16; off; off >>= 1)
                acc[tg] += __shfl_xor_sync(0xFFFFFFFFu, acc[tg], off);
        }
        float v = acc[0];
        #pragma unroll
        for (int tg = 1; tg < 7; tg++) if (lane == tg) v = acc[tg];
        if (lane < 7) g_feats[m * 7 + lane] = v + bs[lane];
    }
}

// ============================================================
// 5) Viterbi: 1 CTA, thread b = batch. 3-bit-packed backpointers
//    in smem (256x64 u32 = 64KB) -> cheap backtrace.
//    out = [path as float (B*T)] ++ [score (B)]
// ============================================================
__global__ void __launch_bounds__(64)
viterbi_kernel(const float* __restrict__ trans, float* __restrict__ out)
{
    extern __shared__ unsigned int bp_s[];   // [256][64]
    __shared__ float tr[49];
    int b = threadIdx.x;                     // 0..63
    if (b < 49) tr[b] = trans[b];
    __syncthreads();

    float v[7];
    #pragma unroll
    for (int k = 0; k < 7; k++) v[k] = (k == 5) ? 0.0f : NEG_;  // START=5

    for (int t = 0; t < 256; t++) {
        const float* f = g_feats + ((size_t)t * 64 + b) * 7;
        float fv[7];
        #pragma unroll
        for (int k = 0; k < 7; k++) fv[k] = f[k];

        unsigned int word = 0;
        float nv[7];
        #pragma unroll
        for (int nx = 0; nx < 7; nx++) {
            float best = v[0] + tr[nx * 7 + 0];
            int arg = 0;
            #pragma unroll
            for (int pv = 1; pv < 7; pv++) {
                float sc = v[pv] + tr[nx * 7 + pv];
                if (sc > best) { best = sc; arg = pv; }
            }
            nv[nx] = best + fv[nx];
            word |= ((unsigned int)arg) << (3 * nx);
        }
        #pragma unroll
        for (int k = 0; k < 7; k++) v[k] = nv[k];
        bp_s[t * 64 + b] = word;
    }

    // termination: + trans[STOP=6][:]
    float best = v[0] + tr[6 * 7 + 0];
    int last = 0;
    #pragma unroll
    for (int k = 1; k < 7; k++) {
        float sc = v[k] + tr[6 * 7 + k];
        if (sc > best) { best = sc; last = k; }
    }
    out[16384 + b] = best;                   // path score

    int tag = last;
    out[(size_t)b * 256 + 255] = (float)tag;
    for (int t = 254; t >= 0; t--) {
        unsigned int w = bp_s[(t + 1) * 64 + b];
        tag = (int)((w >> (3 * tag)) & 7u);
        out[(size_t)b * 256 + t] = (float)tag;
    }
}

// ============================================================
// launcher
// ============================================================
extern "C" void kernel_launch(void* const* d_in, const int* in_sizes, int n_in,
                              void* d_out, int out_size)
{
    (void)in_sizes; (void)n_in; (void)out_size;
    const int*   sent  = (const int*)  d_in[0];
    const float* emb   = (const float*)d_in[1];
    const float* w_ih  = (const float*)d_in[2];
    const float* w_hh  = (const float*)d_in[3];
    const float* b_ih  = (const float*)d_in[4];
    const float* b_hh  = (const float*)d_in[5];
    const float* w_out = (const float*)d_in[6];
    const float* b_out = (const float*)d_in[7];
    const float* trans = (const float*)d_in[8];
    const float* h0    = (const float*)d_in[9];
    const float* c0    = (const float*)d_in[10];
    float* out = (float*)d_out;

    cudaFuncSetAttribute(lstm_kernel, cudaFuncAttributeMaxDynamicSharedMemorySize,
                         LSTM_SMEM_BYTES);
    cudaFuncSetAttribute(viterbi_kernel, cudaFuncAttributeMaxDynamicSharedMemorySize,
                         VIT_SMEM_BYTES);

    embed_kernel<<<256, 256>>>(sent, emb);
    for (int l = 0; l < 2; l++) {
        gemm_kernel<<<dim3(16, 128), 256>>>(w_ih + (size_t)l * 2048 * 512,
                                            b_ih + l * 2048,
                                            b_hh + l * 2048, l);
        lstm_kernel<<<128, 256, LSTM_SMEM_BYTES>>>(w_hh + (size_t)l * 2 * 1024 * 256,
                                                   h0, c0, l);
    }
    feats_kernel<<<256, 256>>>(w_out, b_out);
    viterbi_kernel<<<1, 64, VIT_SMEM_BYTES>>>(trans, out);
}

// round 8
// speedup vs baseline: 1.1294x; 1.1294x over previous
#include <cuda_runtime.h>
#include <cuda_bf16.h>
#include <cstdint>

// Problem: T=256, B=64, E=512, H=512, HD=256, L=2, K=7
#define NEG_ -10000.0f

// ---------------- device scratch (no cudaMalloc allowed) ----------------
__device__ float g_x [16384*512];   // embedded input (layer0 GEMM A)
__device__ float g_y0[16384*512];   // layer0 hidden output [m][dir*256+hd]
__device__ float g_y1[16384*512];   // layer1 hidden output
__device__ float g_xg[16384*2048];  // input-gate preacts [m][dir*1024 + gate*256 + hd]
__device__ float g_feats[16384*7];

// smem sizes
#define LSTM_SMEM_BYTES ((128*260 + 2*8*260) * 4)   /* 149760 */
#define VIT_SMEM_BYTES  (256*64*4)                  /* 65536  */

// ============================================================
// 1) Embedding gather: g_x[t*64+b][:] = emb[sent[t*64+b]][:]
// ============================================================
__global__ void __launch_bounds__(256) embed_kernel(const int* __restrict__ sent,
                                                    const float* __restrict__ emb)
{
    int gw   = (blockIdx.x * 256 + threadIdx.x) >> 5;
    int lane = threadIdx.x & 31;
    int nw   = gridDim.x * 8;
    for (int row = gw; row < 16384; row += nw) {
        int tok = sent[row];
        const float4* s = (const float4*)(emb + (size_t)tok * 512);
        float4*       d = (float4*)(g_x + (size_t)row * 512);
        #pragma unroll
        for (int i = 0; i < 4; i++) d[lane + i * 32] = s[lane + i * 32];
    }
}

// ============================================================
// 2) GEMM: g_xg[m][n] = A[m][:] . W[n][:] + b1[n] + b2[n]
//    A = g_x (layer0) or g_y0 (layer1), [16384][512]
//    W = w_ih[l] as [2048][512] row-major
//    128x128 tile, BK=8, 256 threads, 8x8 microtile (split 4+4)
// ============================================================
__global__ void __launch_bounds__(256, 2)
gemm_kernel(const float* __restrict__ W, const float* __restrict__ b1,
            const float* __restrict__ b2, int layer)
{
    const float* A = layer ? g_y0 : g_x;
    __shared__ float As[8][132];
    __shared__ float Bs[8][132];

    int tid  = threadIdx.x;
    int m0   = blockIdx.y * 128;
    int n0   = blockIdx.x * 128;
    int lrow = tid >> 1;            // 0..127
    int kc   = (tid & 1) * 4;       // 0 or 4
    const float* Ap = A + (size_t)(m0 + lrow) * 512 + kc;
    const float* Wp = W + (size_t)(n0 + lrow) * 512 + kc;
    int tr = tid >> 4;              // 0..15
    int tc = tid & 15;              // 0..15

    float acc[8][8];
    #pragma unroll
    for (int i = 0; i < 8; i++)
        #pragma unroll
        for (int j = 0; j < 8; j++) acc[i][j] = 0.f;

    float4 pa = *(const float4*)Ap;
    float4 pb = *(const float4*)Wp;

    for (int kt = 0; kt < 64; kt++) {
        __syncthreads();
        As[kc + 0][lrow] = pa.x; As[kc + 1][lrow] = pa.y;
        As[kc + 2][lrow] = pa.z; As[kc + 3][lrow] = pa.w;
        Bs[kc + 0][lrow] = pb.x; Bs[kc + 1][lrow] = pb.y;
        Bs[kc + 2][lrow] = pb.z; Bs[kc + 3][lrow] = pb.w;
        __syncthreads();
        if (kt < 63) {
            pa = *(const float4*)(Ap + (kt + 1) * 8);
            pb = *(const float4*)(Wp + (kt + 1) * 8);
        }
        #pragma unroll
        for (int kk = 0; kk < 8; kk++) {
            float4 alo = *(const float4*)&As[kk][tr * 4];
            float4 ahi = *(const float4*)&As[kk][64 + tr * 4];
            float4 blo = *(const float4*)&Bs[kk][tc * 4];
            float4 bhi = *(const float4*)&Bs[kk][64 + tc * 4];
            float av[8] = {alo.x, alo.y, alo.z, alo.w, ahi.x, ahi.y, ahi.z, ahi.w};
            float bv[8] = {blo.x, blo.y, blo.z, blo.w, bhi.x, bhi.y, bhi.z, bhi.w};
            #pragma unroll
            for (int i = 0; i < 8; i++)
                #pragma unroll
                for (int j = 0; j < 8; j++) acc[i][j] += av[i] * bv[j];
        }
    }

    #pragma unroll
    for (int i = 0; i < 8; i++) {
        int r = m0 + ((i < 4) ? (tr * 4 + i) : (64 + tr * 4 + i - 4));
        #pragma unroll
        for (int jh = 0; jh < 2; jh++) {
            int cb = n0 + jh * 64 + tc * 4;
            float4 o;
            o.x = acc[i][jh * 4 + 0] + b1[cb + 0] + b2[cb + 0];
            o.y = acc[i][jh * 4 + 1] + b1[cb + 1] + b2[cb + 1];
            o.z = acc[i][jh * 4 + 2] + b1[cb + 2] + b2[cb + 2];
            o.w = acc[i][jh * 4 + 3] + b1[cb + 3] + b2[cb + 3];
            *(float4*)(g_xg + (size_t)r * 2048 + cb) = o;
        }
    }
}

// ============================================================
// 3) LSTM recurrence, one layer (both directions).
//    128 CTAs = 16 clusters of 8. cluster = (dir, batch-chunk of 8).
//    CTA rank r owns hd in [r*32, r*32+32) for all 4 gates.
//    W_hh slice (128 rows x 256) in smem fp32, padded rows.
//    h exchanged via DSMEM: each thread pushes its h value into all
//    8 cluster CTAs' smem (st.shared::cluster), then barrier.cluster
//    (arrive=release / wait=acquire) publishes + syncs. No gmem, no
//    __threadfence, no L2 round trip on the critical path.
// ============================================================
__device__ __forceinline__ float sigf(float x) { return 1.0f / (1.0f + __expf(-x)); }

__device__ __forceinline__ void st_cluster_f32(uint32_t laddr, int rank, float v) {
    uint32_t raddr;
    asm volatile("mapa.shared::cluster.u32 %0, %1, %2;" : "=r"(raddr) : "r"(laddr), "r"(rank));
    asm volatile("st.shared::cluster.f32 [%0], %1;" :: "r"(raddr), "f"(v) : "memory");
}

__global__ void __cluster_dims__(8, 1, 1) __launch_bounds__(256, 1)
lstm_kernel(const float* __restrict__ w_hh,   // layer base: [2][1024][256]
            const float* __restrict__ h0,     // [4][64][256]
            const float* __restrict__ c0,
            int layer)
{
    extern __shared__ float smem[];
    float* W_s   = smem;                 // 128 rows x 260 floats (padded)
    float* h_loc = smem + 128 * 260;     // [2 parity][8 b][260 floats]
    const int GSTR = 260;

    float* y = layer ? g_y1 : g_y0;

    int bx  = blockIdx.x;
    int cid = bx >> 3;                   // cluster id 0..15
    int r   = bx & 7;                    // rank = hd-chunk
    int dir = cid & 1;
    int bc  = cid >> 1;                  // batch chunk 0..7
    int tid = threadIdx.x;
    int hd  = tid >> 3;                  // 0..31
    int b   = tid & 7;                   // 0..7
    int hd_g = r * 32 + hd;              // 0..255
    int b_g  = bc * 8 + b;               // 0..63

    // load W_hh slice: local row = gate*32 + hd  ->  global row gate*256 + hd_g
    const float* Wd = w_hh + (size_t)dir * 1024 * 256;
    for (int i = tid; i < 128 * 64; i += 256) {
        int row = i >> 6, k4 = i & 63;
        int grow = (row >> 5) * 256 + r * 32 + (row & 31);
        float4 v = *(const float4*)(Wd + (size_t)grow * 256 + k4 * 4);
        *(float4*)(W_s + row * GSTR + k4 * 4) = v;
    }
    // initial h (parity 0) from h0 row (2*layer+dir), batches bc*8..bc*8+7
    const float* h0d = h0 + ((size_t)(2 * layer + dir) * 64 + bc * 8) * 256;
    for (int i = tid; i < 512; i += 256) {
        int row = i >> 6, k4 = i & 63;
        float4 v = *(const float4*)(h0d + row * 256 + k4 * 4);
        *(float4*)(h_loc + row * GSTR + k4 * 4) = v;
    }
    float c = c0[((size_t)(2 * layer + dir) * 64 + b_g) * 256 + hd_g];
    __syncthreads();

    uint32_t h_base = (uint32_t)__cvta_generic_to_shared(h_loc);

    const float* w0r = W_s + (hd) * GSTR;
    const float* w1r = W_s + (32 + hd) * GSTR;
    const float* w2r = W_s + (64 + hd) * GSTR;
    const float* w3r = W_s + (96 + hd) * GSTR;

    for (int s = 0; s < 256; s++) {
        int t = dir ? (255 - s) : s;
        int p = s & 1;
        const float* hrow = h_loc + p * 8 * GSTR + b * GSTR;

        // prefetch input-gate preacts (overlaps with the dot loop)
        size_t xb = ((size_t)t * 64 + b_g) * 2048 + (size_t)dir * 1024 + hd_g;
        float xg0 = g_xg[xb];
        float xg1 = g_xg[xb + 256];
        float xg2 = g_xg[xb + 512];
        float xg3 = g_xg[xb + 768];

        float a0 = 0.f, a1 = 0.f, a2 = 0.f, a3 = 0.f;
        #pragma unroll 8
        for (int k4 = 0; k4 < 64; k4++) {
            float4 hv = *(const float4*)(hrow + k4 * 4);
            float4 w0 = *(const float4*)(w0r + k4 * 4);
            float4 w1 = *(const float4*)(w1r + k4 * 4);
            float4 w2 = *(const float4*)(w2r + k4 * 4);
            float4 w3 = *(const float4*)(w3r + k4 * 4);
            a0 += w0.x * hv.x + w0.y * hv.y + w0.z * hv.z + w0.w * hv.w;
            a1 += w1.x * hv.x + w1.y * hv.y + w1.z * hv.z + w1.w * hv.w;
            a2 += w2.x * hv.x + w2.y * hv.y + w2.z * hv.z + w2.w * hv.w;
            a3 += w3.x * hv.x + w3.y * hv.y + w3.z * hv.z + w3.w * hv.w;
        }
        float ig = sigf(a0 + xg0);
        float fg = sigf(a1 + xg1);
        float gg = tanhf(a2 + xg2);
        float og = sigf(a3 + xg3);
        c = fg * c + ig * gg;
        float h = og * tanhf(c);

        // push h to all 8 cluster CTAs' smem (including our own)
        int wp = (s + 1) & 1;
        uint32_t dst = h_base + (uint32_t)(((wp * 8 + b) * GSTR + hd_g) * 4);
        #pragma unroll
        for (int rk = 0; rk < 8; rk++) st_cluster_f32(dst, rk, h);

        // write layer output (overlaps with DSMEM drain)
        y[((size_t)t * 64 + b_g) * 512 + (size_t)dir * 256 + hd_g] = h;

        // release our stores, acquire everyone else's; also CTA-wide sync
        asm volatile("barrier.cluster.arrive.aligned;" ::: "memory");
        asm volatile("barrier.cluster.wait.aligned;"   ::: "memory");
    }
}

// ============================================================
// 4) hidden2tag: g_feats[m][k] = g_y1[m][:] . w_out[k][:] + b_out[k]
// ============================================================
__global__ void __launch_bounds__(256)
feats_kernel(const float* __restrict__ w_out, const float* __restrict__ b_out)
{
    __shared__ float ws[7 * 512];
    __shared__ float bs[7];
    int tid = threadIdx.x;
    for (int i = tid; i < 3584; i += 256) ws[i] = w_out[i];
    if (tid < 7) bs[tid] = b_out[tid];
    __syncthreads();

    int gw   = (blockIdx.x * 256 + tid) >> 5;
    int lane = tid & 31;
    int nw   = gridDim.x * 8;
    for (int m = gw; m < 16384; m += nw) {
        const float4* y4 = (const float4*)(g_y1 + (size_t)m * 512);
        float acc[7] = {0, 0, 0, 0, 0, 0, 0};
        #pragma unroll
        for (int q = 0; q < 4; q++) {
            int k4 = q * 32 + lane;
            float4 yv = y4[k4];
            #pragma unroll
            for (int tg = 0; tg < 7; tg++) {
                float4 wv = *(const float4*)(ws + tg * 512 + k4 * 4);
                acc[tg] += yv.x * wv.x + yv.y * wv.y + yv.z * wv.z + yv.w * wv.w;
            }
        }
        #pragma unroll
        for (int tg = 0; tg < 7; tg++) {
            #pragma unroll
            for (int off = 16; off; off >>= 1)
                acc[tg] += __shfl_xor_sync(0xFFFFFFFFu, acc[tg], off);
        }
        float v = acc[0];
        #pragma unroll
        for (int tg = 1; tg < 7; tg++) if (lane == tg) v = acc[tg];
        if (lane < 7) g_feats[m * 7 + lane] = v + bs[lane];
    }
}

// ============================================================
// 5) Viterbi: 1 CTA, thread b = batch. 3-bit-packed backpointers
//    in smem (256x64 u32 = 64KB) -> cheap backtrace.
//    out = [path as float (B*T)] ++ [score (B)]
// ============================================================
__global__ void __launch_bounds__(64)
viterbi_kernel(const float* __restrict__ trans, float* __restrict__ out)
{
    extern __shared__ unsigned int bp_s[];   // [256][64]
    __shared__ float tr[49];
    int b = threadIdx.x;                     // 0..63
    if (b < 49) tr[b] = trans[b];
    __syncthreads();

    float v[7];
    #pragma unroll
    for (int k = 0; k < 7; k++) v[k] = (k == 5) ? 0.0f : NEG_;  // START=5

    for (int t = 0; t < 256; t++) {
        const float* f = g_feats + ((size_t)t * 64 + b) * 7;
        float fv[7];
        #pragma unroll
        for (int k = 0; k < 7; k++) fv[k] = f[k];

        unsigned int word = 0;
        float nv[7];
        #pragma unroll
        for (int nx = 0; nx < 7; nx++) {
            float best = v[0] + tr[nx * 7 + 0];
            int arg = 0;
            #pragma unroll
            for (int pv = 1; pv < 7; pv++) {
                float sc = v[pv] + tr[nx * 7 + pv];
                if (sc > best) { best = sc; arg = pv; }
            }
            nv[nx] = best + fv[nx];
            word |= ((unsigned int)arg) << (3 * nx);
        }
        #pragma unroll
        for (int k = 0; k < 7; k++) v[k] = nv[k];
        bp_s[t * 64 + b] = word;
    }

    // termination: + trans[STOP=6][:]
    float best = v[0] + tr[6 * 7 + 0];
    int last = 0;
    #pragma unroll
    for (int k = 1; k < 7; k++) {
        float sc = v[k] + tr[6 * 7 + k];
        if (sc > best) { best = sc; last = k; }
    }
    out[16384 + b] = best;                   // path score

    int tag = last;
    out[(size_t)b * 256 + 255] = (float)tag;
    for (int t = 254; t >= 0; t--) {
        unsigned int w = bp_s[(t + 1) * 64 + b];
        tag = (int)((w >> (3 * tag)) & 7u);
        out[(size_t)b * 256 + t] = (float)tag;
    }
}

// ============================================================
// launcher
// ============================================================
extern "C" void kernel_launch(void* const* d_in, const int* in_sizes, int n_in,
                              void* d_out, int out_size)
{
    (void)in_sizes; (void)n_in; (void)out_size;
    const int*   sent  = (const int*)  d_in[0];
    const float* emb   = (const float*)d_in[1];
    const float* w_ih  = (const float*)d_in[2];
    const float* w_hh  = (const float*)d_in[3];
    const float* b_ih  = (const float*)d_in[4];
    const float* b_hh  = (const float*)d_in[5];
    const float* w_out = (const float*)d_in[6];
    const float* b_out = (const float*)d_in[7];
    const float* trans = (const float*)d_in[8];
    const float* h0    = (const float*)d_in[9];
    const float* c0    = (const float*)d_in[10];
    float* out = (float*)d_out;

    cudaFuncSetAttribute(lstm_kernel, cudaFuncAttributeMaxDynamicSharedMemorySize,
                         LSTM_SMEM_BYTES);
    cudaFuncSetAttribute(viterbi_kernel, cudaFuncAttributeMaxDynamicSharedMemorySize,
                         VIT_SMEM_BYTES);

    embed_kernel<<<256, 256>>>(sent, emb);
    for (int l = 0; l < 2; l++) {
        gemm_kernel<<<dim3(16, 128), 256>>>(w_ih + (size_t)l * 2048 * 512,
                                            b_ih + l * 2048,
                                            b_hh + l * 2048, l);
        lstm_kernel<<<128, 256, LSTM_SMEM_BYTES>>>(w_hh + (size_t)l * 2 * 1024 * 256,
                                                   h0, c0, l);
    }
    feats_kernel<<<256, 256>>>(w_out, b_out);
    viterbi_kernel<<<1, 64, VIT_SMEM_BYTES>>>(trans, out);
}

// round 9
// speedup vs baseline: 1.1386x; 1.0082x over previous
#include <cuda_runtime.h>
#include <cuda_bf16.h>
#include <cstdint>

// Problem: T=256, B=64, E=512, H=512, HD=256, L=2, K=7
#define NEG_ -10000.0f

// packed f32x2 helpers (sm_103a)
#define FMA2(d, a, b) asm("fma.rn.f32x2 %0, %1, %2, %0;" : "+l"(d) : "l"(a), "l"(b))
#define PACK2(out, v) asm("mov.b64 %0, {%1, %1};" : "=l"(out) : "r"(__float_as_uint(v)))
#define UNPK2(lo, hi, in) asm("mov.b64 {%0, %1}, %2;" : "=r"(lo), "=r"(hi) : "l"(in))

// ---------------- device scratch (no cudaMalloc allowed) ----------------
__device__ float g_x [16384*512];   // embedded input (layer0 GEMM A)
__device__ float g_y0[16384*512];   // layer0 hidden output [m][dir*256+hd]
__device__ float g_y1[16384*512];   // layer1 hidden output
__device__ float g_xg[16384*2048];  // input-gate preacts [m][dir*1024 + gate*256 + hd]
__device__ float g_feats[16384*7];

// LSTM smem layout: W rows 128 x 276 floats, h rows 16 x 276 floats.
// Row = 276 floats; K-half 0 at col 0..127, K-half 1 at col 144..271.
// (276 mod 32 = 20 -> 8-distinct bank groups across rows; 144 mod 32 = 16
//  keeps the two K-halves of the 4 gate rows on disjoint bank groups.)
#define GSTR  276
#define KSOFF 144
#define LSTM_SMEM_BYTES (144*276*4)   /* 158976 */
#define VIT_SMEM_BYTES  (256*64*4)    /* 65536  */

// ============================================================
// 1) Embedding gather
// ============================================================
__global__ void __launch_bounds__(256) embed_kernel(const int* __restrict__ sent,
                                                    const float* __restrict__ emb)
{
    int gw   = (blockIdx.x * 256 + threadIdx.x) >> 5;
    int lane = threadIdx.x & 31;
    int nw   = gridDim.x * 8;
    for (int row = gw; row < 16384; row += nw) {
        int tok = sent[row];
        const float4* s = (const float4*)(emb + (size_t)tok * 512);
        float4*       d = (float4*)(g_x + (size_t)row * 512);
        #pragma unroll
        for (int i = 0; i < 4; i++) d[lane + i * 32] = s[lane + i * 32];
    }
}

// ============================================================
// 2) GEMM: g_xg[m][n] = A[m][:] . W[n][:] + b1[n] + b2[n]
//    128x128 tile, BK=8, 256 threads, 8x8 microtile via f32x2 FMA,
//    double-buffered smem (one __syncthreads per k-tile).
// ============================================================
__global__ void __launch_bounds__(256, 2)
gemm_kernel(const float* __restrict__ W, const float* __restrict__ b1,
            const float* __restrict__ b2, int layer)
{
    const float* A = layer ? g_y0 : g_x;
    __shared__ __align__(16) float As[2][8][132];
    __shared__ __align__(16) float Bs[2][8][132];

    int tid  = threadIdx.x;
    int m0   = blockIdx.y * 128;
    int n0   = blockIdx.x * 128;
    int lrow = tid >> 1;            // 0..127
    int kc   = (tid & 1) * 4;       // 0 or 4
    const float* Ap = A + (size_t)(m0 + lrow) * 512 + kc;
    const float* Wp = W + (size_t)(n0 + lrow) * 512 + kc;
    int tr = tid >> 4;              // 0..15
    int tc = tid & 15;              // 0..15

    unsigned long long acc2[8][4];
    #pragma unroll
    for (int i = 0; i < 8; i++)
        #pragma unroll
        for (int j = 0; j < 4; j++) acc2[i][j] = 0ull;

    // preload k-tile 0 into buffer 0
    {
        float4 pa = *(const float4*)Ap;
        float4 pb = *(const float4*)Wp;
        As[0][kc + 0][lrow] = pa.x; As[0][kc + 1][lrow] = pa.y;
        As[0][kc + 2][lrow] = pa.z; As[0][kc + 3][lrow] = pa.w;
        Bs[0][kc + 0][lrow] = pb.x; Bs[0][kc + 1][lrow] = pb.y;
        Bs[0][kc + 2][lrow] = pb.z; Bs[0][kc + 3][lrow] = pb.w;
    }
    __syncthreads();

    for (int kt = 0; kt < 64; kt++) {
        int cur = kt & 1;
        float4 na, nb;
        if (kt < 63) {
            na = *(const float4*)(Ap + (kt + 1) * 8);
            nb = *(const float4*)(Wp + (kt + 1) * 8);
        }
        #pragma unroll
        for (int kk = 0; kk < 8; kk++) {
            float4 alo = *(const float4*)&As[cur][kk][tr * 4];
            float4 ahi = *(const float4*)&As[cur][kk][64 + tr * 4];
            ulonglong2 bl = *(const ulonglong2*)&Bs[cur][kk][tc * 4];
            ulonglong2 bh = *(const ulonglong2*)&Bs[cur][kk][64 + tc * 4];
            float av[8] = {alo.x, alo.y, alo.z, alo.w, ahi.x, ahi.y, ahi.z, ahi.w};
            #pragma unroll
            for (int i = 0; i < 8; i++) {
                unsigned long long a2;
                PACK2(a2, av[i]);
                FMA2(acc2[i][0], a2, bl.x);
                FMA2(acc2[i][1], a2, bl.y);
                FMA2(acc2[i][2], a2, bh.x);
                FMA2(acc2[i][3], a2, bh.y);
            }
        }
        if (kt < 63) {
            int nxt = cur ^ 1;
            As[nxt][kc + 0][lrow] = na.x; As[nxt][kc + 1][lrow] = na.y;
            As[nxt][kc + 2][lrow] = na.z; As[nxt][kc + 3][lrow] = na.w;
            Bs[nxt][kc + 0][lrow] = nb.x; Bs[nxt][kc + 1][lrow] = nb.y;
            Bs[nxt][kc + 2][lrow] = nb.z; Bs[nxt][kc + 3][lrow] = nb.w;
            __syncthreads();
        }
    }

    #pragma unroll
    for (int i = 0; i < 8; i++) {
        int r = m0 + ((i < 4) ? (tr * 4 + i) : (64 + tr * 4 + i - 4));
        #pragma unroll
        for (int jh = 0; jh < 2; jh++) {
            int cb = n0 + jh * 64 + tc * 4;
            unsigned int u0, u1, u2, u3;
            UNPK2(u0, u1, acc2[i][jh * 2 + 0]);
            UNPK2(u2, u3, acc2[i][jh * 2 + 1]);
            float4 o;
            o.x = __uint_as_float(u0) + b1[cb + 0] + b2[cb + 0];
            o.y = __uint_as_float(u1) + b1[cb + 1] + b2[cb + 1];
            o.z = __uint_as_float(u2) + b1[cb + 2] + b2[cb + 2];
            o.w = __uint_as_float(u3) + b1[cb + 3] + b2[cb + 3];
            *(float4*)(g_xg + (size_t)r * 2048 + cb) = o;
        }
    }
}

// ============================================================
// 3) LSTM recurrence (one layer, both dirs).
//    128 CTAs = 16 clusters of 8; cluster = (dir, 8-batch chunk);
//    CTA rank r owns hd in [r*32, r*32+32).
//    Thread (hd 0..31, bp 0..3, ks 0..1): 4 gates x 2 batches over
//    half of K (128), f32x2 FMA, shfl.bfly(1) K-reduce; epilogue
//    batch = bp*2+ks. h exchanged via DSMEM st.shared::cluster with
//    precomputed mapa addresses + barrier.cluster.
// ============================================================
__device__ __forceinline__ float sigf(float x) { return 1.0f / (1.0f + __expf(-x)); }

__global__ void __cluster_dims__(8, 1, 1) __launch_bounds__(256, 1)
lstm_kernel(const float* __restrict__ w_hh,   // layer base: [2][1024][256]
            const float* __restrict__ h0,     // [4][64][256]
            const float* __restrict__ c0,
            int layer)
{
    extern __shared__ float smem[];
    float* W_s   = smem;                 // 128 rows x GSTR
    float* h_loc = smem + 128 * GSTR;    // 16 rows (2 parity x 8 b) x GSTR

    float* y = layer ? g_y1 : g_y0;

    int bx  = blockIdx.x;
    int cid = bx >> 3;                   // 0..15
    int r   = bx & 7;                    // hd-chunk rank
    int dir = cid & 1;
    int bc  = cid >> 1;                  // batch chunk 0..7
    int tid = threadIdx.x;
    int hd  = tid >> 3;                  // 0..31
    int bp  = (tid >> 1) & 3;            // batch pair 0..3
    int ks  = tid & 1;                   // K-half
    int hd_g = r * 32 + hd;
    int b_ep = bp * 2 + ks;              // epilogue batch within chunk
    int b_g  = bc * 8 + b_ep;

    // ---- load W_hh slice into split-row layout ----
    const float* Wd = w_hh + (size_t)dir * 1024 * 256;
    for (int i = tid; i < 128 * 64; i += 256) {
        int row = i >> 6, q = i & 63;
        int grow = (row >> 5) * 256 + r * 32 + (row & 31);
        float4 v = *(const float4*)(Wd + (size_t)grow * 256 + q * 4);
        int col = (q < 32) ? q * 4 : KSOFF + (q - 32) * 4;
        *(float4*)(W_s + row * GSTR + col) = v;
    }
    // ---- initial h (parity 0) ----
    const float* h0d = h0 + ((size_t)(2 * layer + dir) * 64 + bc * 8) * 256;
    for (int i = tid; i < 512; i += 256) {
        int row = i >> 6, q = i & 63;
        float4 v = *(const float4*)(h0d + row * 256 + q * 4);
        int col = (q < 32) ? q * 4 : KSOFF + (q - 32) * 4;
        *(float4*)(h_loc + row * GSTR + col) = v;
    }
    float c = c0[((size_t)(2 * layer + dir) * 64 + b_g) * 256 + hd_g];
    __syncthreads();

    // precompute DSMEM push addresses (parity 0) for all 8 ranks
    uint32_t h_base = (uint32_t)__cvta_generic_to_shared(h_loc);
    int col_hd = (hd_g < 128) ? hd_g : KSOFF + (hd_g - 128);
    uint32_t dst0 = h_base + (uint32_t)((b_ep * GSTR + col_hd) * 4);
    uint32_t rka[8];
    #pragma unroll
    for (int rk = 0; rk < 8; rk++)
        asm("mapa.shared::cluster.u32 %0, %1, %2;" : "=r"(rka[rk]) : "r"(dst0), "r"(rk));
    const uint32_t PAR_OFF = 8u * GSTR * 4u;

    const float* w0r = W_s + (hd)      * GSTR + ks * KSOFF;
    const float* w1r = W_s + (32 + hd) * GSTR + ks * KSOFF;
    const float* w2r = W_s + (64 + hd) * GSTR + ks * KSOFF;
    const float* w3r = W_s + (96 + hd) * GSTR + ks * KSOFF;
    const float* hb  = h_loc + bp * 2 * GSTR + ks * KSOFF;

    for (int s = 0; s < 256; s++) {
        int t  = dir ? (255 - s) : s;
        int p  = s & 1;
        int wp = p ^ 1;

        // prefetch input-gate preacts for epilogue batch
        size_t xb = ((size_t)t * 64 + b_g) * 2048 + (size_t)dir * 1024 + hd_g;
        float xg0 = g_xg[xb];
        float xg1 = g_xg[xb + 256];
        float xg2 = g_xg[xb + 512];
        float xg3 = g_xg[xb + 768];

        const float* hr0 = hb + p * 8 * GSTR;        // batch bp*2
        const float* hr1 = hr0 + GSTR;               // batch bp*2+1

        unsigned long long a00 = 0, a01 = 0, a10 = 0, a11 = 0;
        unsigned long long a20 = 0, a21 = 0, a30 = 0, a31 = 0;
        #pragma unroll 8
        for (int k4 = 0; k4 < 32; k4++) {
            ulonglong2 h0v = *(const ulonglong2*)(hr0 + k4 * 4);
            ulonglong2 h1v = *(const ulonglong2*)(hr1 + k4 * 4);
            ulonglong2 w0v = *(const ulonglong2*)(w0r + k4 * 4);
            ulonglong2 w1v = *(const ulonglong2*)(w1r + k4 * 4);
            ulonglong2 w2v = *(const ulonglong2*)(w2r + k4 * 4);
            ulonglong2 w3v = *(const ulonglong2*)(w3r + k4 * 4);
            FMA2(a00, w0v.x, h0v.x); FMA2(a00, w0v.y, h0v.y);
            FMA2(a01, w0v.x, h1v.x); FMA2(a01, w0v.y, h1v.y);
            FMA2(a10, w1v.x, h0v.x); FMA2(a10, w1v.y, h0v.y);
            FMA2(a11, w1v.x, h1v.x); FMA2(a11, w1v.y, h1v.y);
            FMA2(a20, w2v.x, h0v.x); FMA2(a20, w2v.y, h0v.y);
            FMA2(a21, w2v.x, h1v.x); FMA2(a21, w2v.y, h1v.y);
            FMA2(a30, w3v.x, h0v.x); FMA2(a30, w3v.y, h0v.y);
            FMA2(a31, w3v.x, h1v.x); FMA2(a31, w3v.y, h1v.y);
        }

        // fold f32x2 halves, then K-half reduce with partner lane (ks^1)
        float d0, d1, d2, d3;
        {
            unsigned int lo, hi; float v0, v1;
            UNPK2(lo, hi, a00); v0 = __uint_as_float(lo) + __uint_as_float(hi);
            UNPK2(lo, hi, a01); v1 = __uint_as_float(lo) + __uint_as_float(hi);
            v0 += __shfl_xor_sync(0xFFFFFFFFu, v0, 1);
            v1 += __shfl_xor_sync(0xFFFFFFFFu, v1, 1);
            d0 = ks ? v1 : v0;
            UNPK2(lo, hi, a10); v0 = __uint_as_float(lo) + __uint_as_float(hi);
            UNPK2(lo, hi, a11); v1 = __uint_as_float(lo) + __uint_as_float(hi);
            v0 += __shfl_xor_sync(0xFFFFFFFFu, v0, 1);
            v1 += __shfl_xor_sync(0xFFFFFFFFu, v1, 1);
            d1 = ks ? v1 : v0;
            UNPK2(lo, hi, a20); v0 = __uint_as_float(lo) + __uint_as_float(hi);
            UNPK2(lo, hi, a21); v1 = __uint_as_float(lo) + __uint_as_float(hi);
            v0 += __shfl_xor_sync(0xFFFFFFFFu, v0, 1);
            v1 += __shfl_xor_sync(0xFFFFFFFFu, v1, 1);
            d2 = ks ? v1 : v0;
            UNPK2(lo, hi, a30); v0 = __uint_as_float(lo) + __uint_as_float(hi);
            UNPK2(lo, hi, a31); v1 = __uint_as_float(lo) + __uint_as_float(hi);
            v0 += __shfl_xor_sync(0xFFFFFFFFu, v0, 1);
            v1 += __shfl_xor_sync(0xFFFFFFFFu, v1, 1);
            d3 = ks ? v1 : v0;
        }

        float ig = sigf(d0 + xg0);
        float fg = sigf(d1 + xg1);
        float gg = tanhf(d2 + xg2);
        float og = sigf(d3 + xg3);
        c = fg * c + ig * gg;
        float h = og * tanhf(c);

        // layer output
        y[((size_t)t * 64 + b_g) * 512 + (size_t)dir * 256 + hd_g] = h;

        // push h into all 8 cluster CTAs' smem (precomputed addresses)
        uint32_t poff = wp ? PAR_OFF : 0u;
        #pragma unroll
        for (int rk = 0; rk < 8; rk++)
            asm volatile("st.shared::cluster.f32 [%0], %1;"
                         :: "r"(rka[rk] + poff), "f"(h) : "memory");

        asm volatile("barrier.cluster.arrive.aligned;" ::: "memory");
        asm volatile("barrier.cluster.wait.aligned;"   ::: "memory");
    }
}

// ============================================================
// 4) hidden2tag
// ============================================================
__global__ void __launch_bounds__(256)
feats_kernel(const float* __restrict__ w_out, const float* __restrict__ b_out)
{
    __shared__ float ws[7 * 512];
    __shared__ float bs[7];
    int tid = threadIdx.x;
    for (int i = tid; i < 3584; i += 256) ws[i] = w_out[i];
    if (tid < 7) bs[tid] = b_out[tid];
    __syncthreads();

    int gw   = (blockIdx.x * 256 + tid) >> 5;
    int lane = tid & 31;
    int nw   = gridDim.x * 8;
    for (int m = gw; m < 16384; m += nw) {
        const float4* y4 = (const float4*)(g_y1 + (size_t)m * 512);
        float acc[7] = {0, 0, 0, 0, 0, 0, 0};
        #pragma unroll
        for (int q = 0; q < 4; q++) {
            int k4 = q * 32 + lane;
            float4 yv = y4[k4];
            #pragma unroll
            for (int tg = 0; tg < 7; tg++) {
                float4 wv = *(const float4*)(ws + tg * 512 + k4 * 4);
                acc[tg] += yv.x * wv.x + yv.y * wv.y + yv.z * wv.z + yv.w * wv.w;
            }
        }
        #pragma unroll
        for (int tg = 0; tg < 7; tg++) {
            #pragma unroll
            for (int off = 16; off; off >>= 1)
                acc[tg] += __shfl_xor_sync(0xFFFFFFFFu, acc[tg], off);
        }
        float v = acc[0];
        #pragma unroll
        for (int tg = 1; tg < 7; tg++) if (lane == tg) v = acc[tg];
        if (lane < 7) g_feats[m * 7 + lane] = v + bs[lane];
    }
}

// ============================================================
// 5) Viterbi: 1 CTA, thread = batch; packed backpointers in smem.
//    out = [path as float (B*T)] ++ [score (B)]
// ============================================================
__global__ void __launch_bounds__(64)
viterbi_kernel(const float* __restrict__ trans, float* __restrict__ out)
{
    extern __shared__ unsigned int bp_s[];   // [256][64]
    __shared__ float tr[49];
    int b = threadIdx.x;
    if (b < 49) tr[b] = trans[b];
    __syncthreads();

    float v[7];
    #pragma unroll
    for (int k = 0; k < 7; k++) v[k] = (k == 5) ? 0.0f : NEG_;  // START=5

    for (int t = 0; t < 256; t++) {
        const float* f = g_feats + ((size_t)t * 64 + b) * 7;
        float fv[7];
        #pragma unroll
        for (int k = 0; k < 7; k++) fv[k] = f[k];

        unsigned int word = 0;
        float nv[7];
        #pragma unroll
        for (int nx = 0; nx < 7; nx++) {
            float best = v[0] + tr[nx * 7 + 0];
            int arg = 0;
            #pragma unroll
            for (int pv = 1; pv < 7; pv++) {
                float sc = v[pv] + tr[nx * 7 + pv];
                if (sc > best) { best = sc; arg = pv; }
            }
            nv[nx] = best + fv[nx];
            word |= ((unsigned int)arg) << (3 * nx);
        }
        #pragma unroll
        for (int k = 0; k < 7; k++) v[k] = nv[k];
        bp_s[t * 64 + b] = word;
    }

    float best = v[0] + tr[6 * 7 + 0];
    int last = 0;
    #pragma unroll
    for (int k = 1; k < 7; k++) {
        float sc = v[k] + tr[6 * 7 + k];
        if (sc > best) { best = sc; last = k; }
    }
    out[16384 + b] = best;

    int tag = last;
    out[(size_t)b * 256 + 255] = (float)tag;
    for (int t = 254; t >= 0; t--) {
        unsigned int w = bp_s[(t + 1) * 64 + b];
        tag = (int)((w >> (3 * tag)) & 7u);
        out[(size_t)b * 256 + t] = (float)tag;
    }
}

// ============================================================
// launcher
// ============================================================
extern "C" void kernel_launch(void* const* d_in, const int* in_sizes, int n_in,
                              void* d_out, int out_size)
{
    (void)in_sizes; (void)n_in; (void)out_size;
    const int*   sent  = (const int*)  d_in[0];
    const float* emb   = (const float*)d_in[1];
    const float* w_ih  = (const float*)d_in[2];
    const float* w_hh  = (const float*)d_in[3];
    const float* b_ih  = (const float*)d_in[4];
    const float* b_hh  = (const float*)d_in[5];
    const float* w_out = (const float*)d_in[6];
    const float* b_out = (const float*)d_in[7];
    const float* trans = (const float*)d_in[8];
    const float* h0    = (const float*)d_in[9];
    const float* c0    = (const float*)d_in[10];
    float* out = (float*)d_out;

    cudaFuncSetAttribute(lstm_kernel, cudaFuncAttributeMaxDynamicSharedMemorySize,
                         LSTM_SMEM_BYTES);
    cudaFuncSetAttribute(viterbi_kernel, cudaFuncAttributeMaxDynamicSharedMemorySize,
                         VIT_SMEM_BYTES);

    embed_kernel<<<256, 256>>>(sent, emb);
    for (int l = 0; l < 2; l++) {
        gemm_kernel<<<dim3(16, 128), 256>>>(w_ih + (size_t)l * 2048 * 512,
                                            b_ih + l * 2048,
                                            b_hh + l * 2048, l);
        lstm_kernel<<<128, 256, LSTM_SMEM_BYTES>>>(w_hh + (size_t)l * 2 * 1024 * 256,
                                                   h0, c0, l);
    }
    feats_kernel<<<256, 256>>>(w_out, b_out);
    viterbi_kernel<<<1, 64, VIT_SMEM_BYTES>>>(trans, out);
}